// round 15
// baseline (speedup 1.0000x reference)
#include <cuda_runtime.h>
#include <cuda_fp16.h>
#include <math.h>
#include <stdint.h>

#define HID   2048
#define DOWND 512
#define NE    16
#define NTOK  8192
#define NPAIR (NTOK*2)

// ---------------- scratch (static device memory; no allocs allowed) ----------------
__device__ float  g_comb[NTOK*DOWND];      // combined expert outputs (fp32, atomic)
__device__ __half g_xh[NTOK*HID];          // x as fp16
__device__ __half g_wh[NE*DOWND*HID];      // down_w fp16
__device__ __half g_uh[HID*DOWND];         // up_w fp16
__device__ __half g_hh[NTOK*DOWND];        // gelu(combined) fp16
__device__ int   g_pair_tok[NPAIR];
__device__ float g_pair_w [NPAIR];
__device__ int   g_ei[NTOK*2];
__device__ float g_wp[NTOK*2];
__device__ int   g_cnt[NE];
__device__ int   g_off[NE];
__device__ float g_sum[NE];

// ---------------- PTX helpers (Ampere-class: valid on compute_103 base) ----------------
__device__ __forceinline__ uint32_t smem_u32(const void* p){
    uint32_t a;
    asm("{ .reg .u64 t; cvta.to.shared.u64 t, %1; cvt.u32.u64 %0, t; }" : "=r"(a) : "l"(p));
    return a;
}
__device__ __forceinline__ void cpa16(uint32_t saddr, const void* g){
    asm volatile("cp.async.cg.shared.global [%0], [%1], 16;" :: "r"(saddr), "l"(g));
}
__device__ __forceinline__ void ldm_x4(uint32_t* r, uint32_t addr){
    asm volatile("ldmatrix.sync.aligned.m8n8.x4.shared.b16 {%0,%1,%2,%3}, [%4];"
        : "=r"(r[0]), "=r"(r[1]), "=r"(r[2]), "=r"(r[3]) : "r"(addr));
}
__device__ __forceinline__ void mma16816(float* c, const uint32_t* a, const uint32_t* b){
    asm volatile("mma.sync.aligned.m16n8k16.row.col.f32.f16.f16.f32 "
        "{%0,%1,%2,%3}, {%4,%5,%6,%7}, {%8,%9}, {%0,%1,%2,%3};"
        : "+f"(c[0]), "+f"(c[1]), "+f"(c[2]), "+f"(c[3])
        : "r"(a[0]), "r"(a[1]), "r"(a[2]), "r"(a[3]), "r"(b[0]), "r"(b[1]));
}

__device__ __forceinline__ float gelu_new(float v){
    float c = v + 0.044715f * v * v * v;
    return 0.5f * v * (1.0f + tanhf(0.7978845608028654f * c));
}

// ---------------- merged zero + weight conversion (all low-register bandwidth work) ----
#define N4_DW (NE*DOWND*HID/4)
#define N4_UW (HID*DOWND/4)
#define ZERO_BLKS (NTOK*DOWND/4/256)                 // 4096
#define CVT_BLKS  ((N4_DW + N4_UW + 255)/256)        // 17408
__global__ void k_zerocvt(float* __restrict__ comb,
                          const float* __restrict__ dw, __half* __restrict__ wh,
                          const float* __restrict__ uw, __half* __restrict__ uh){
    int b = blockIdx.x;
    int tid = threadIdx.x;
    if (b == 0 && tid < NE){ g_cnt[tid] = 0; g_sum[tid] = 0.0f; }
    if (b < ZERO_BLKS){
        int i = b * 256 + tid;
        ((float4*)comb)[i] = make_float4(0.f, 0.f, 0.f, 0.f);
    } else {
        int i = (b - ZERO_BLKS) * 256 + tid;
        const float* in; __half* h; int idx;
        if (i < N4_DW){ in = dw; h = wh; idx = i; }
        else if (i < N4_DW + N4_UW){ in = uw; h = uh; idx = i - N4_DW; }
        else return;
        float4 v = ((const float4*)in)[idx];
        ((__half2*)h)[2*idx]   = __floats2half2_rn(v.x, v.y);
        ((__half2*)h)[2*idx+1] = __floats2half2_rn(v.z, v.w);
    }
}

// ---------------- gate: 4 tokens per warp; routing + x fp16 (R12-identical) ----------
__global__ void k_gate(const float* __restrict__ x, const float* __restrict__ gw,
                       __half* __restrict__ xh){
    int warp = threadIdx.x >> 5;
    int lane = threadIdx.x & 31;
    int n0 = (blockIdx.x * 8 + warp) * 4;      // 4 tokens per warp
    const float4* x4 = (const float4*)x;
    const float4* g4 = (const float4*)gw;
    float acc[4][NE];
#pragma unroll
    for (int t = 0; t < 4; t++)
#pragma unroll
        for (int e = 0; e < NE; e++) acc[t][e] = 0.0f;

    for (int i = 0; i < 16; i++){
        int j = lane + 32*i;
        float4 xv[4];
#pragma unroll
        for (int t = 0; t < 4; t++){
            xv[t] = x4[(size_t)(n0+t)*(HID/4) + j];
            size_t o = (size_t)(n0+t)*HID + (size_t)j*4;
            ((__half2*)(xh + o))[0] = __floats2half2_rn(xv[t].x, xv[t].y);
            ((__half2*)(xh + o))[1] = __floats2half2_rn(xv[t].z, xv[t].w);
        }
#pragma unroll
        for (int e = 0; e < NE; e++){
            float4 gv = g4[e*(HID/4) + j];
#pragma unroll
            for (int t = 0; t < 4; t++)
                acc[t][e] += xv[t].x*gv.x + xv[t].y*gv.y + xv[t].z*gv.z + xv[t].w*gv.w;
        }
    }
#pragma unroll
    for (int t = 0; t < 4; t++)
#pragma unroll
        for (int e = 0; e < NE; e++){
#pragma unroll
            for (int o = 16; o > 0; o >>= 1)
                acc[t][e] += __shfl_xor_sync(0xffffffffu, acc[t][e], o);
        }
    if (lane == 0){
#pragma unroll
        for (int t = 0; t < 4; t++){
            int n = n0 + t;
            float v0 = -1e30f, v1 = -1e30f; int i0 = 0, i1 = 0;
#pragma unroll
            for (int e = 0; e < NE; e++){
                float v = acc[t][e];
                if (v > v0){ v1 = v0; i1 = i0; v0 = v; i0 = e; }
                else if (v > v1){ v1 = v; i1 = e; }
            }
            float ee = expf(v1 - v0);
            float s  = 1.0f + ee;
            float w0 = 1.0f / s, w1 = ee / s;
            g_ei[2*n]   = i0; g_ei[2*n+1] = i1;
            g_wp[2*n]   = w0; g_wp[2*n+1] = w1;
            atomicAdd(&g_cnt[i0], 1);  atomicAdd(&g_cnt[i1], 1);
            atomicAdd(&g_sum[i0], w0); atomicAdd(&g_sum[i1], w1);
        }
    }
}

// ---------------- fused prefix + loss + scatter (one small launch) ----------------
__global__ void __launch_bounds__(256)
k_ps(float* __restrict__ loss_out){
    __shared__ int s_cur[NE];
    int tid = threadIdx.x;
    if (tid == 0){
        int a = 0; float ls = 0.0f;
        for (int e = 0; e < NE; e++){
            g_off[e] = a; s_cur[e] = a; a += g_cnt[e];
            float t = g_sum[e] / (float)NTOK;
            ls += t * t;
        }
        *loss_out = (float)NE * ls * 0.1f;
    }
    __syncthreads();
    for (int i = tid; i < NTOK*2; i += 256){
        int e = g_ei[i];
        int p = atomicAdd(&s_cur[e], 1);
        g_pair_tok[p] = i >> 1;
        g_pair_w [p]  = g_wp[i];
    }
}

// ---------------- warp-MMA GEMM (single fp16, fp32 accum) — R12-identical ------------
// Block 128x128, BK=64, 4 warps (2x2), warp tile 64x64. 3-stage cp.async pipeline,
// intra-kt ldmatrix fragment double-buffering.
#define STAGE_BYTES 32768
#define OFF_A 0
#define OFF_B 16384
#define GSMEM  (3*STAGE_BYTES)

template<bool EXPERT, int KDIM>
__global__ void __launch_bounds__(128, 2)
k_gemm(const __half* __restrict__ A, const __half* __restrict__ B,
       const float* __restrict__ bias, float* __restrict__ C)
{
    int e   = EXPERT ? blockIdx.z : 0;
    int cnt = EXPERT ? g_cnt[e] : NTOK;
    int m0  = blockIdx.x * 128;
    if (m0 >= cnt) return;
    int base = EXPERT ? g_off[e] : 0;
    int n0   = blockIdx.y * 128;
    const float* bptr = EXPERT ? bias + e*DOWND : bias;

    extern __shared__ char smem[];
    uint32_t sm = smem_u32(smem);
    __shared__ int s_aoff[128];
    __shared__ int s_atok[128];
    __shared__ int s_boff[128];

    int tid  = threadIdx.x;
    int lane = tid & 31;
    int wid  = tid >> 5;
    int wm   = wid >> 1;
    int wn   = wid & 1;

    {
        int m = m0 + tid;
        int ar;
        if (EXPERT){
            ar = g_pair_tok[base + ((m < cnt) ? m : 0)];
            s_atok[tid] = ar;
        } else {
            ar = m;
        }
        s_aoff[tid] = ar * KDIM;
        int bn = (EXPERT ? e*DOWND : 0) + n0 + tid;
        s_boff[tid] = bn * KDIM;
    }
    __syncthreads();

    const int NK = KDIM / 64;   // 32 expert, 8 up

    auto copy_stage = [&](int kt, int buf){
        uint32_t st = sm + buf*STAGE_BYTES;
        int kbase = kt*64;
        int c  = tid & 7;
        int rb = tid >> 3;
#pragma unroll
        for (int i = 0; i < 8; i++){
            int row = rb + i*16;
            uint32_t soff = (uint32_t)row*128u + (uint32_t)((c ^ (row & 7))<<4);
            cpa16(st + OFF_A + soff, A + s_aoff[row] + kbase + c*8);
        }
#pragma unroll
        for (int i = 0; i < 8; i++){
            int row = rb + i*16;
            uint32_t soff = (uint32_t)row*128u + (uint32_t)((c ^ (row & 7))<<4);
            cpa16(st + OFF_B + soff, B + s_boff[row] + kbase + c*8);
        }
    };

    copy_stage(0, 0);
    asm volatile("cp.async.commit_group;" ::: "memory");
    copy_stage(1, 1);
    asm volatile("cp.async.commit_group;" ::: "memory");
    copy_stage(2, 2);
    asm volatile("cp.async.commit_group;" ::: "memory");

    float acc[4][8][4];
#pragma unroll
    for (int a = 0; a < 4; a++)
#pragma unroll
        for (int b = 0; b < 8; b++)
#pragma unroll
            for (int c = 0; c < 4; c++) acc[a][b][c] = 0.0f;

    int arow0 = wm*64 + (lane & 15);
    int achk  = lane >> 4;
    int bgrp  = lane >> 3;
    int brow0 = wn*64 + (bgrp >> 1)*8 + (lane & 7);
    int bchk  = bgrp & 1;

    uint32_t fa[2][4][4], fb[2][4][4];
    auto load_frags = [&](int ks, uint32_t st, uint32_t (*fA)[4], uint32_t (*fB)[4]){
#pragma unroll
        for (int mt = 0; mt < 4; mt++){
            int r  = arow0 + mt*16;
            int ch = ks*2 + achk;
            uint32_t sa = (uint32_t)r*128u + (uint32_t)(((ch ^ (r & 7)) & 7)<<4);
            ldm_x4(fA[mt], st + OFF_A + sa);
        }
#pragma unroll
        for (int ntp = 0; ntp < 4; ntp++){
            int r  = brow0 + ntp*16;
            int ch = ks*2 + bchk;
            uint32_t sb = (uint32_t)r*128u + (uint32_t)(((ch ^ (r & 7)) & 7)<<4);
            ldm_x4(fB[ntp], st + OFF_B + sb);
        }
    };

    for (int kt = 0; kt < NK; kt++){
        if (kt + 2 < NK)      asm volatile("cp.async.wait_group 2;" ::: "memory");
        else if (kt + 1 < NK) asm volatile("cp.async.wait_group 1;" ::: "memory");
        else                  asm volatile("cp.async.wait_group 0;" ::: "memory");
        __syncthreads();

        uint32_t st = sm + (kt % 3)*STAGE_BYTES;
        load_frags(0, st, fa[0], fb[0]);
#pragma unroll
        for (int ks = 0; ks < 4; ks++){
            int cur = ks & 1;
            if (ks < 3) load_frags(ks + 1, st, fa[cur^1], fb[cur^1]);
#pragma unroll
            for (int ntp = 0; ntp < 4; ntp++){
#pragma unroll
                for (int mt = 0; mt < 4; mt++){
                    mma16816(acc[mt][2*ntp  ], fa[cur][mt], fb[cur][ntp]    );
                    mma16816(acc[mt][2*ntp+1], fa[cur][mt], fb[cur][ntp] + 2);
                }
            }
        }
        __syncthreads();
        if (kt + 3 < NK){
            copy_stage(kt + 3, (kt + 3) % 3);
            asm volatile("cp.async.commit_group;" ::: "memory");
        }
    }

    // epilogue
    int g   = lane >> 2;
    int tgi = lane & 3;
#pragma unroll
    for (int mt = 0; mt < 4; mt++){
#pragma unroll
        for (int h = 0; h < 2; h++){
            int r = wm*64 + mt*16 + g + h*8;
            int m = m0 + r;
            if (EXPERT && m >= cnt) continue;
            if (EXPERT){
                // scatter-add w*(acc+bias) into combined token buffer.
                // Exactly 2 contributions per element onto a zeroed buffer ->
                // order-independent fp32 result.
                float w = g_pair_w[base + m];
                size_t rowbase = (size_t)s_atok[r] * DOWND;
#pragma unroll
                for (int nt = 0; nt < 8; nt++){
                    int col = n0 + wn*64 + nt*8 + tgi*2;
                    float2 v;
                    v.x = (acc[mt][nt][2*h+0] + __ldg(bptr + col    )) * w;
                    v.y = (acc[mt][nt][2*h+1] + __ldg(bptr + col + 1)) * w;
                    atomicAdd((float2*)&C[rowbase + col], v);
                }
            } else {
                size_t rowbase = (size_t)m * HID;
#pragma unroll
                for (int nt = 0; nt < 8; nt++){
                    int col = n0 + wn*64 + nt*8 + tgi*2;
                    float2 v;
                    v.x = acc[mt][nt][2*h+0] + __ldg(bptr + col    );
                    v.y = acc[mt][nt][2*h+1] + __ldg(bptr + col + 1);
                    *(float2*)&C[rowbase + col] = v;
                }
            }
        }
    }
}

// ---------------- gelu over combined buffer -> fp16 ----------------
__global__ void k_combine(const float* __restrict__ comb, __half* __restrict__ hh){
    int i = blockIdx.x * blockDim.x + threadIdx.x;
    float4 v = ((const float4*)comb)[i];
    float g0 = gelu_new(v.x);
    float g1 = gelu_new(v.y);
    float g2 = gelu_new(v.z);
    float g3 = gelu_new(v.w);
    ((__half2*)hh)[2*i]   = __floats2half2_rn(g0, g1);
    ((__half2*)hh)[2*i+1] = __floats2half2_rn(g2, g3);
}

// ---------------- launch ----------------
extern "C" void kernel_launch(void* const* d_in, const int* in_sizes, int n_in,
                              void* d_out, int out_size){
    const float* x      = (const float*)d_in[0];
    const float* gate_w = (const float*)d_in[1];
    const float* down_w = (const float*)d_in[2];
    const float* down_b = (const float*)d_in[3];
    const float* up_w   = (const float*)d_in[4];
    const float* up_b   = (const float*)d_in[5];
    float* out = (float*)d_out;

    void *p_xh, *p_wh, *p_uh, *p_hh, *p_comb;
    cudaGetSymbolAddress(&p_xh,   g_xh);
    cudaGetSymbolAddress(&p_wh,   g_wh);
    cudaGetSymbolAddress(&p_uh,   g_uh);
    cudaGetSymbolAddress(&p_hh,   g_hh);
    cudaGetSymbolAddress(&p_comb, g_comb);

    cudaFuncSetAttribute(k_gemm<true,  HID>,   cudaFuncAttributeMaxDynamicSharedMemorySize, GSMEM);
    cudaFuncSetAttribute(k_gemm<false, DOWND>, cudaFuncAttributeMaxDynamicSharedMemorySize, GSMEM);

    // merged zero + cnt/sum init + weight conversions (one bandwidth launch)
    k_zerocvt<<<ZERO_BLKS + CVT_BLKS, 256>>>((float*)p_comb,
                                             down_w, (__half*)p_wh,
                                             up_w,   (__half*)p_uh);
    k_gate<<<NTOK/32, 256>>>(x, gate_w, (__half*)p_xh);
    k_ps<<<1, 256>>>(out + (size_t)NTOK * HID);   // prefix + loss + scatter

    // grouped expert GEMM with fused scatter-add combine (R12 static grid)
    dim3 ge(64, DOWND/128, NE);
    k_gemm<true, HID><<<ge, 128, GSMEM>>>(
        (const __half*)p_xh, (const __half*)p_wh, down_b, (float*)p_comb);

    k_combine<<<(NTOK*DOWND/4)/256, 256>>>((const float*)p_comb, (__half*)p_hh);

    // up projection: out = h . up_w^T + up_b
    dim3 gu(NTOK/128, HID/128);
    k_gemm<false, DOWND><<<gu, 128, GSMEM>>>(
        (const __half*)p_hh, (const __half*)p_uh, up_b, out);
}

// round 16
// speedup vs baseline: 1.1436x; 1.1436x over previous
#include <cuda_runtime.h>
#include <cuda_fp16.h>
#include <math.h>
#include <stdint.h>

#define HID   2048
#define DOWND 512
#define NE    16
#define NTOK  8192
#define NPAIR (NTOK*2)

// ---------------- scratch (static device memory; no allocs allowed) ----------------
__device__ float  g_comb[NTOK*DOWND];      // combined expert outputs (fp32, atomic)
__device__ __half g_xh[NTOK*HID];          // x as fp16
__device__ __half g_wh[NE*DOWND*HID];      // down_w fp16
__device__ __half g_uh[HID*DOWND];         // up_w fp16
__device__ __half g_hh[NTOK*DOWND];        // gelu(combined) fp16
__device__ int   g_pair_tok[NPAIR];
__device__ float g_pair_w [NPAIR];
__device__ int   g_ei[NTOK*2];
__device__ float g_wp[NTOK*2];
__device__ int   g_cnt[NE];
__device__ int   g_off[NE];
__device__ int   g_cur[NE];
__device__ float g_sum[NE];

// ---------------- PTX helpers (Ampere-class: valid on compute_103 base) ----------------
__device__ __forceinline__ uint32_t smem_u32(const void* p){
    uint32_t a;
    asm("{ .reg .u64 t; cvta.to.shared.u64 t, %1; cvt.u32.u64 %0, t; }" : "=r"(a) : "l"(p));
    return a;
}
__device__ __forceinline__ void cpa16(uint32_t saddr, const void* g){
    asm volatile("cp.async.cg.shared.global [%0], [%1], 16;" :: "r"(saddr), "l"(g));
}
__device__ __forceinline__ void ldm_x4(uint32_t* r, uint32_t addr){
    asm volatile("ldmatrix.sync.aligned.m8n8.x4.shared.b16 {%0,%1,%2,%3}, [%4];"
        : "=r"(r[0]), "=r"(r[1]), "=r"(r[2]), "=r"(r[3]) : "r"(addr));
}
__device__ __forceinline__ void mma16816(float* c, const uint32_t* a, const uint32_t* b){
    asm volatile("mma.sync.aligned.m16n8k16.row.col.f32.f16.f16.f32 "
        "{%0,%1,%2,%3}, {%4,%5,%6,%7}, {%8,%9}, {%0,%1,%2,%3};"
        : "+f"(c[0]), "+f"(c[1]), "+f"(c[2]), "+f"(c[3])
        : "r"(a[0]), "r"(a[1]), "r"(a[2]), "r"(a[3]), "r"(b[0]), "r"(b[1]));
}

__device__ __forceinline__ float gelu_new(float v){
    float c = v + 0.044715f * v * v * v;
    return 0.5f * v * (1.0f + tanhf(0.7978845608028654f * c));
}

// ---------------- zero combine buffer + routing init (R12-identical) ----------------
__global__ void k_zero(float* __restrict__ c){
    int i = blockIdx.x * blockDim.x + threadIdx.x;
    ((float4*)c)[i] = make_float4(0.f, 0.f, 0.f, 0.f);
    if (blockIdx.x == 0 && threadIdx.x < NE){
        g_cnt[threadIdx.x] = 0; g_sum[threadIdx.x] = 0.0f;
    }
}

// ---------------- gate: 4 tokens per warp; routing + x fp16 (R12-identical) ----------
__global__ void k_gate(const float* __restrict__ x, const float* __restrict__ gw,
                       __half* __restrict__ xh){
    int warp = threadIdx.x >> 5;
    int lane = threadIdx.x & 31;
    int n0 = (blockIdx.x * 8 + warp) * 4;      // 4 tokens per warp
    const float4* x4 = (const float4*)x;
    const float4* g4 = (const float4*)gw;
    float acc[4][NE];
#pragma unroll
    for (int t = 0; t < 4; t++)
#pragma unroll
        for (int e = 0; e < NE; e++) acc[t][e] = 0.0f;

    for (int i = 0; i < 16; i++){
        int j = lane + 32*i;
        float4 xv[4];
#pragma unroll
        for (int t = 0; t < 4; t++){
            xv[t] = x4[(size_t)(n0+t)*(HID/4) + j];
            size_t o = (size_t)(n0+t)*HID + (size_t)j*4;
            ((__half2*)(xh + o))[0] = __floats2half2_rn(xv[t].x, xv[t].y);
            ((__half2*)(xh + o))[1] = __floats2half2_rn(xv[t].z, xv[t].w);
        }
#pragma unroll
        for (int e = 0; e < NE; e++){
            float4 gv = g4[e*(HID/4) + j];
#pragma unroll
            for (int t = 0; t < 4; t++)
                acc[t][e] += xv[t].x*gv.x + xv[t].y*gv.y + xv[t].z*gv.z + xv[t].w*gv.w;
        }
    }
#pragma unroll
    for (int t = 0; t < 4; t++)
#pragma unroll
        for (int e = 0; e < NE; e++){
#pragma unroll
            for (int o = 16; o > 0; o >>= 1)
                acc[t][e] += __shfl_xor_sync(0xffffffffu, acc[t][e], o);
        }
    if (lane == 0){
#pragma unroll
        for (int t = 0; t < 4; t++){
            int n = n0 + t;
            float v0 = -1e30f, v1 = -1e30f; int i0 = 0, i1 = 0;
#pragma unroll
            for (int e = 0; e < NE; e++){
                float v = acc[t][e];
                if (v > v0){ v1 = v0; i1 = i0; v0 = v; i0 = e; }
                else if (v > v1){ v1 = v; i1 = e; }
            }
            float ee = expf(v1 - v0);
            float s  = 1.0f + ee;
            float w0 = 1.0f / s, w1 = ee / s;
            g_ei[2*n]   = i0; g_ei[2*n+1] = i1;
            g_wp[2*n]   = w0; g_wp[2*n+1] = w1;
            atomicAdd(&g_cnt[i0], 1);  atomicAdd(&g_cnt[i1], 1);
            atomicAdd(&g_sum[i0], w0); atomicAdd(&g_sum[i1], w1);
        }
    }
}

__global__ void k_prefix(float* __restrict__ loss_out){
    if (threadIdx.x == 0 && blockIdx.x == 0){
        int a = 0; float ls = 0.0f;
        for (int e = 0; e < NE; e++){
            g_off[e] = a; g_cur[e] = a; a += g_cnt[e];
            float t = g_sum[e] / (float)NTOK;
            ls += t * t;
        }
        *loss_out = (float)NE * ls * 0.1f;
    }
}

__global__ void k_scatter(){
    int n = blockIdx.x * blockDim.x + threadIdx.x;
    if (n >= NTOK) return;
#pragma unroll
    for (int s = 0; s < 2; s++){
        int e = g_ei[2*n+s];
        int p = atomicAdd(&g_cur[e], 1);
        g_pair_tok[p] = n;
        g_pair_w [p]  = g_wp[2*n+s];
    }
}

// ---------------- fp32 -> fp16 conversion (both weight tensors; R12-identical) --------
#define N4_DW (NE*DOWND*HID/4)
#define N4_UW (HID*DOWND/4)
__global__ void k_cvt1(const float* __restrict__ dw, __half* __restrict__ wh,
                       const float* __restrict__ uw, __half* __restrict__ uh){
    int i = blockIdx.x * blockDim.x + threadIdx.x;
    const float* in; __half* h; int idx;
    if (i < N4_DW){ in = dw; h = wh; idx = i; }
    else if (i < N4_DW + N4_UW){ in = uw; h = uh; idx = i - N4_DW; }
    else return;
    float4 v = ((const float4*)in)[idx];
    ((__half2*)h)[2*idx]   = __floats2half2_rn(v.x, v.y);
    ((__half2*)h)[2*idx+1] = __floats2half2_rn(v.z, v.w);
}

// ---------------- warp-MMA GEMM (single fp16, fp32 accum) -----------------------------
// NEW in R16: block 128x128, BK=64, **8 warps (4x2), warp tile 32x64**, 256 threads.
// acc 64 regs/thread, no frag double-buffering -> <=128 regs -> 16 warps/SM (4/SMSP).
// 3-stage cp.async pipeline, same swizzle as R12.
#define STAGE_BYTES 32768
#define OFF_A 0
#define OFF_B 16384
#define GSMEM  (3*STAGE_BYTES)

template<bool EXPERT, int KDIM>
__global__ void __launch_bounds__(256, 2)
k_gemm(const __half* __restrict__ A, const __half* __restrict__ B,
       const float* __restrict__ bias, float* __restrict__ C)
{
    int e   = EXPERT ? blockIdx.z : 0;
    int cnt = EXPERT ? g_cnt[e] : NTOK;
    int m0  = blockIdx.x * 128;
    if (m0 >= cnt) return;
    int base = EXPERT ? g_off[e] : 0;
    int n0   = blockIdx.y * 128;
    const float* bptr = EXPERT ? bias + e*DOWND : bias;

    extern __shared__ char smem[];
    uint32_t sm = smem_u32(smem);
    __shared__ int s_aoff[128];
    __shared__ int s_atok[128];
    __shared__ int s_boff[128];

    int tid  = threadIdx.x;
    int lane = tid & 31;
    int wid  = tid >> 5;
    int wm   = wid >> 1;      // 0..3 (M, 32-row slices)
    int wn   = wid & 1;       // 0..1 (N, 64-col slices)

    if (tid < 128){
        int m = m0 + tid;
        int ar;
        if (EXPERT){
            ar = g_pair_tok[base + ((m < cnt) ? m : 0)];
            s_atok[tid] = ar;
        } else {
            ar = m;
        }
        s_aoff[tid] = ar * KDIM;
        int bn = (EXPERT ? e*DOWND : 0) + n0 + tid;
        s_boff[tid] = bn * KDIM;
    }
    __syncthreads();

    const int NK = KDIM / 64;   // 32 expert, 8 up

    auto copy_stage = [&](int kt, int buf){
        uint32_t st = sm + buf*STAGE_BYTES;
        int kbase = kt*64;
        int c  = tid & 7;
        int rb = tid >> 3;           // 0..31
#pragma unroll
        for (int i = 0; i < 4; i++){
            int row = rb + i*32;
            uint32_t soff = (uint32_t)row*128u + (uint32_t)((c ^ (row & 7))<<4);
            cpa16(st + OFF_A + soff, A + s_aoff[row] + kbase + c*8);
        }
#pragma unroll
        for (int i = 0; i < 4; i++){
            int row = rb + i*32;
            uint32_t soff = (uint32_t)row*128u + (uint32_t)((c ^ (row & 7))<<4);
            cpa16(st + OFF_B + soff, B + s_boff[row] + kbase + c*8);
        }
    };

    copy_stage(0, 0);
    asm volatile("cp.async.commit_group;" ::: "memory");
    copy_stage(1, 1);
    asm volatile("cp.async.commit_group;" ::: "memory");
    copy_stage(2, 2);
    asm volatile("cp.async.commit_group;" ::: "memory");

    float acc[2][8][4];
#pragma unroll
    for (int a = 0; a < 2; a++)
#pragma unroll
        for (int b = 0; b < 8; b++)
#pragma unroll
            for (int c = 0; c < 4; c++) acc[a][b][c] = 0.0f;

    int arow0 = wm*32 + (lane & 15);
    int achk  = lane >> 4;                       // 0/1
    int bgrp  = lane >> 3;                       // 0..3
    int brow0 = wn*64 + (bgrp >> 1)*8 + (lane & 7);
    int bchk  = bgrp & 1;                        // 0/1

    for (int kt = 0; kt < NK; kt++){
        if (kt + 2 < NK)      asm volatile("cp.async.wait_group 2;" ::: "memory");
        else if (kt + 1 < NK) asm volatile("cp.async.wait_group 1;" ::: "memory");
        else                  asm volatile("cp.async.wait_group 0;" ::: "memory");
        __syncthreads();

        uint32_t st = sm + (kt % 3)*STAGE_BYTES;
#pragma unroll
        for (int ks = 0; ks < 4; ks++){
            uint32_t fa[2][4], fb[4][4];
#pragma unroll
            for (int mt = 0; mt < 2; mt++){
                int r  = arow0 + mt*16;
                int ch = ks*2 + achk;
                uint32_t sa = (uint32_t)r*128u + (uint32_t)(((ch ^ (r & 7)) & 7)<<4);
                ldm_x4(fa[mt], st + OFF_A + sa);
            }
#pragma unroll
            for (int ntp = 0; ntp < 4; ntp++){
                int r  = brow0 + ntp*16;
                int ch = ks*2 + bchk;
                uint32_t sb = (uint32_t)r*128u + (uint32_t)(((ch ^ (r & 7)) & 7)<<4);
                ldm_x4(fb[ntp], st + OFF_B + sb);
            }
#pragma unroll
            for (int ntp = 0; ntp < 4; ntp++){
#pragma unroll
                for (int mt = 0; mt < 2; mt++){
                    mma16816(acc[mt][2*ntp  ], fa[mt], fb[ntp]    );
                    mma16816(acc[mt][2*ntp+1], fa[mt], fb[ntp] + 2);
                }
            }
        }
        __syncthreads();
        if (kt + 3 < NK){
            copy_stage(kt + 3, (kt + 3) % 3);
            asm volatile("cp.async.commit_group;" ::: "memory");
        }
    }

    // epilogue
    int g   = lane >> 2;
    int tgi = lane & 3;
#pragma unroll
    for (int mt = 0; mt < 2; mt++){
#pragma unroll
        for (int h = 0; h < 2; h++){
            int r = wm*32 + mt*16 + g + h*8;
            int m = m0 + r;
            if (EXPERT && m >= cnt) continue;
            if (EXPERT){
                // scatter-add w*(acc+bias) into combined token buffer.
                // Exactly 2 contributions per element onto a zeroed buffer ->
                // order-independent fp32 result.
                float w = g_pair_w[base + m];
                size_t rowbase = (size_t)s_atok[r] * DOWND;
#pragma unroll
                for (int nt = 0; nt < 8; nt++){
                    int col = n0 + wn*64 + nt*8 + tgi*2;
                    float2 v;
                    v.x = (acc[mt][nt][2*h+0] + __ldg(bptr + col    )) * w;
                    v.y = (acc[mt][nt][2*h+1] + __ldg(bptr + col + 1)) * w;
                    atomicAdd((float2*)&C[rowbase + col], v);
                }
            } else {
                size_t rowbase = (size_t)m * HID;
#pragma unroll
                for (int nt = 0; nt < 8; nt++){
                    int col = n0 + wn*64 + nt*8 + tgi*2;
                    float2 v;
                    v.x = acc[mt][nt][2*h+0] + __ldg(bptr + col    );
                    v.y = acc[mt][nt][2*h+1] + __ldg(bptr + col + 1);
                    *(float2*)&C[rowbase + col] = v;
                }
            }
        }
    }
}

// ---------------- gelu over combined buffer -> fp16 ----------------
__global__ void k_combine(const float* __restrict__ comb, __half* __restrict__ hh){
    int i = blockIdx.x * blockDim.x + threadIdx.x;
    float4 v = ((const float4*)comb)[i];
    float g0 = gelu_new(v.x);
    float g1 = gelu_new(v.y);
    float g2 = gelu_new(v.z);
    float g3 = gelu_new(v.w);
    ((__half2*)hh)[2*i]   = __floats2half2_rn(g0, g1);
    ((__half2*)hh)[2*i+1] = __floats2half2_rn(g2, g3);
}

// ---------------- launch ----------------
extern "C" void kernel_launch(void* const* d_in, const int* in_sizes, int n_in,
                              void* d_out, int out_size){
    const float* x      = (const float*)d_in[0];
    const float* gate_w = (const float*)d_in[1];
    const float* down_w = (const float*)d_in[2];
    const float* down_b = (const float*)d_in[3];
    const float* up_w   = (const float*)d_in[4];
    const float* up_b   = (const float*)d_in[5];
    float* out = (float*)d_out;

    void *p_xh, *p_wh, *p_uh, *p_hh, *p_comb;
    cudaGetSymbolAddress(&p_xh,   g_xh);
    cudaGetSymbolAddress(&p_wh,   g_wh);
    cudaGetSymbolAddress(&p_uh,   g_uh);
    cudaGetSymbolAddress(&p_hh,   g_hh);
    cudaGetSymbolAddress(&p_comb, g_comb);

    cudaFuncSetAttribute(k_gemm<true,  HID>,   cudaFuncAttributeMaxDynamicSharedMemorySize, GSMEM);
    cudaFuncSetAttribute(k_gemm<false, DOWND>, cudaFuncAttributeMaxDynamicSharedMemorySize, GSMEM);

    // R12-identical preamble
    k_zero<<<(NTOK*DOWND/4)/256, 256>>>((float*)p_comb);
    k_gate<<<NTOK/32, 256>>>(x, gate_w, (__half*)p_xh);
    k_prefix<<<1, 1>>>(out + (size_t)NTOK * HID);   // loss scalar after [B,S,HIDDEN]
    k_scatter<<<NTOK/256, 256>>>();
    k_cvt1<<<(N4_DW + N4_UW + 255)/256, 256>>>(down_w, (__half*)p_wh, up_w, (__half*)p_uh);

    // grouped expert GEMM with fused scatter-add combine (256-thread, 8-warp CTAs)
    dim3 ge(64, DOWND/128, NE);
    k_gemm<true, HID><<<ge, 256, GSMEM>>>(
        (const __half*)p_xh, (const __half*)p_wh, down_b, (float*)p_comb);

    k_combine<<<(NTOK*DOWND/4)/256, 256>>>((const float*)p_comb, (__half*)p_hh);

    // up projection: out = h . up_w^T + up_b
    dim3 gu(NTOK/128, HID/128);
    k_gemm<false, DOWND><<<gu, 256, GSMEM>>>(
        (const __half*)p_hh, (const __half*)p_uh, up_b, out);
}

// round 17
// speedup vs baseline: 1.1881x; 1.0390x over previous
#include <cuda_runtime.h>
#include <cuda_fp16.h>
#include <math.h>
#include <stdint.h>

#define HID   2048
#define DOWND 512
#define NE    16
#define NTOK  8192
#define NPAIR (NTOK*2)

// ---------------- scratch (static device memory; no allocs allowed) ----------------
__device__ float  g_comb[NTOK*DOWND];      // combined expert outputs (fp32, atomic)
__device__ __half g_xh[NTOK*HID];          // x as fp16
__device__ __half g_wh[NE*DOWND*HID];      // down_w fp16
__device__ __half g_uh[HID*DOWND];         // up_w fp16
__device__ __half g_hh[NTOK*DOWND];        // gelu(combined) fp16
__device__ int   g_pair_tok[NPAIR];
__device__ float g_pair_w [NPAIR];
__device__ int   g_ei[NTOK*2];
__device__ float g_wp[NTOK*2];
__device__ int   g_cnt[NE];
__device__ int   g_off[NE];
__device__ int   g_cur[NE];
__device__ float g_sum[NE];

// ---------------- PTX helpers (Ampere-class: valid on compute_103 base) ----------------
__device__ __forceinline__ uint32_t smem_u32(const void* p){
    uint32_t a;
    asm("{ .reg .u64 t; cvta.to.shared.u64 t, %1; cvt.u32.u64 %0, t; }" : "=r"(a) : "l"(p));
    return a;
}
__device__ __forceinline__ void cpa16(uint32_t saddr, const void* g){
    asm volatile("cp.async.cg.shared.global [%0], [%1], 16;" :: "r"(saddr), "l"(g));
}
__device__ __forceinline__ void ldm_x4(uint32_t* r, uint32_t addr){
    asm volatile("ldmatrix.sync.aligned.m8n8.x4.shared.b16 {%0,%1,%2,%3}, [%4];"
        : "=r"(r[0]), "=r"(r[1]), "=r"(r[2]), "=r"(r[3]) : "r"(addr));
}
__device__ __forceinline__ void mma16816(float* c, const uint32_t* a, const uint32_t* b){
    asm volatile("mma.sync.aligned.m16n8k16.row.col.f32.f16.f16.f32 "
        "{%0,%1,%2,%3}, {%4,%5,%6,%7}, {%8,%9}, {%0,%1,%2,%3};"
        : "+f"(c[0]), "+f"(c[1]), "+f"(c[2]), "+f"(c[3])
        : "r"(a[0]), "r"(a[1]), "r"(a[2]), "r"(a[3]), "r"(b[0]), "r"(b[1]));
}

__device__ __forceinline__ float gelu_new(float v){
    float c = v + 0.044715f * v * v * v;
    return 0.5f * v * (1.0f + tanhf(0.7978845608028654f * c));
}

// ---------------- zero combine buffer + routing init (R12-identical) ----------------
__global__ void k_zero(float* __restrict__ c){
    int i = blockIdx.x * blockDim.x + threadIdx.x;
    ((float4*)c)[i] = make_float4(0.f, 0.f, 0.f, 0.f);
    if (blockIdx.x == 0 && threadIdx.x < NE){
        g_cnt[threadIdx.x] = 0; g_sum[threadIdx.x] = 0.0f;
    }
}

// ---------------- gate: 4 tokens per warp; routing + x fp16 (R12-identical) ----------
__global__ void k_gate(const float* __restrict__ x, const float* __restrict__ gw,
                       __half* __restrict__ xh){
    int warp = threadIdx.x >> 5;
    int lane = threadIdx.x & 31;
    int n0 = (blockIdx.x * 8 + warp) * 4;      // 4 tokens per warp
    const float4* x4 = (const float4*)x;
    const float4* g4 = (const float4*)gw;
    float acc[4][NE];
#pragma unroll
    for (int t = 0; t < 4; t++)
#pragma unroll
        for (int e = 0; e < NE; e++) acc[t][e] = 0.0f;

    for (int i = 0; i < 16; i++){
        int j = lane + 32*i;
        float4 xv[4];
#pragma unroll
        for (int t = 0; t < 4; t++){
            xv[t] = x4[(size_t)(n0+t)*(HID/4) + j];
            size_t o = (size_t)(n0+t)*HID + (size_t)j*4;
            ((__half2*)(xh + o))[0] = __floats2half2_rn(xv[t].x, xv[t].y);
            ((__half2*)(xh + o))[1] = __floats2half2_rn(xv[t].z, xv[t].w);
        }
#pragma unroll
        for (int e = 0; e < NE; e++){
            float4 gv = g4[e*(HID/4) + j];
#pragma unroll
            for (int t = 0; t < 4; t++)
                acc[t][e] += xv[t].x*gv.x + xv[t].y*gv.y + xv[t].z*gv.z + xv[t].w*gv.w;
        }
    }
#pragma unroll
    for (int t = 0; t < 4; t++)
#pragma unroll
        for (int e = 0; e < NE; e++){
#pragma unroll
            for (int o = 16; o > 0; o >>= 1)
                acc[t][e] += __shfl_xor_sync(0xffffffffu, acc[t][e], o);
        }
    if (lane == 0){
#pragma unroll
        for (int t = 0; t < 4; t++){
            int n = n0 + t;
            float v0 = -1e30f, v1 = -1e30f; int i0 = 0, i1 = 0;
#pragma unroll
            for (int e = 0; e < NE; e++){
                float v = acc[t][e];
                if (v > v0){ v1 = v0; i1 = i0; v0 = v; i0 = e; }
                else if (v > v1){ v1 = v; i1 = e; }
            }
            float ee = expf(v1 - v0);
            float s  = 1.0f + ee;
            float w0 = 1.0f / s, w1 = ee / s;
            g_ei[2*n]   = i0; g_ei[2*n+1] = i1;
            g_wp[2*n]   = w0; g_wp[2*n+1] = w1;
            atomicAdd(&g_cnt[i0], 1);  atomicAdd(&g_cnt[i1], 1);
            atomicAdd(&g_sum[i0], w0); atomicAdd(&g_sum[i1], w1);
        }
    }
}

__global__ void k_prefix(float* __restrict__ loss_out){
    if (threadIdx.x == 0 && blockIdx.x == 0){
        int a = 0; float ls = 0.0f;
        for (int e = 0; e < NE; e++){
            g_off[e] = a; g_cur[e] = a; a += g_cnt[e];
            float t = g_sum[e] / (float)NTOK;
            ls += t * t;
        }
        *loss_out = (float)NE * ls * 0.1f;
    }
}

__global__ void k_scatter(){
    int n = blockIdx.x * blockDim.x + threadIdx.x;
    if (n >= NTOK) return;
#pragma unroll
    for (int s = 0; s < 2; s++){
        int e = g_ei[2*n+s];
        int p = atomicAdd(&g_cur[e], 1);
        g_pair_tok[p] = n;
        g_pair_w [p]  = g_wp[2*n+s];
    }
}

// ---------------- fp32 -> fp16 conversion (both weight tensors; R12-identical) --------
#define N4_DW (NE*DOWND*HID/4)
#define N4_UW (HID*DOWND/4)
__global__ void k_cvt1(const float* __restrict__ dw, __half* __restrict__ wh,
                       const float* __restrict__ uw, __half* __restrict__ uh){
    int i = blockIdx.x * blockDim.x + threadIdx.x;
    const float* in; __half* h; int idx;
    if (i < N4_DW){ in = dw; h = wh; idx = i; }
    else if (i < N4_DW + N4_UW){ in = uw; h = uh; idx = i - N4_DW; }
    else return;
    float4 v = ((const float4*)in)[idx];
    ((__half2*)h)[2*idx]   = __floats2half2_rn(v.x, v.y);
    ((__half2*)h)[2*idx+1] = __floats2half2_rn(v.z, v.w);
}

// ---------------- warp-MMA GEMM (single fp16, fp32 accum) -----------------------------
// R16 config (block 128x128, BK=64, 8 warps 4x2, warp tile 32x64, 256 threads)
// R17: ONE-barrier multistage pipeline — per kt: wait -> sync -> issue copy kt+2 -> MMA.
// The top-of-loop barrier proves all warps finished reading stage kt-1, whose buffer
// ((kt+2)%3) is the copy target. Copy is in flight during the MMA burst.
#define STAGE_BYTES 32768
#define OFF_A 0
#define OFF_B 16384
#define GSMEM  (3*STAGE_BYTES)

template<bool EXPERT, int KDIM>
__global__ void __launch_bounds__(256, 2)
k_gemm(const __half* __restrict__ A, const __half* __restrict__ B,
       const float* __restrict__ bias, float* __restrict__ C)
{
    int e   = EXPERT ? blockIdx.z : 0;
    int cnt = EXPERT ? g_cnt[e] : NTOK;
    int m0  = blockIdx.x * 128;
    if (m0 >= cnt) return;
    int base = EXPERT ? g_off[e] : 0;
    int n0   = blockIdx.y * 128;
    const float* bptr = EXPERT ? bias + e*DOWND : bias;

    extern __shared__ char smem[];
    uint32_t sm = smem_u32(smem);
    __shared__ int s_aoff[128];
    __shared__ int s_atok[128];
    __shared__ int s_boff[128];

    int tid  = threadIdx.x;
    int lane = tid & 31;
    int wid  = tid >> 5;
    int wm   = wid >> 1;      // 0..3 (M, 32-row slices)
    int wn   = wid & 1;       // 0..1 (N, 64-col slices)

    if (tid < 128){
        int m = m0 + tid;
        int ar;
        if (EXPERT){
            ar = g_pair_tok[base + ((m < cnt) ? m : 0)];
            s_atok[tid] = ar;
        } else {
            ar = m;
        }
        s_aoff[tid] = ar * KDIM;
        int bn = (EXPERT ? e*DOWND : 0) + n0 + tid;
        s_boff[tid] = bn * KDIM;
    }
    __syncthreads();

    const int NK = KDIM / 64;   // 32 expert, 8 up

    auto copy_stage = [&](int kt, int buf){
        uint32_t st = sm + buf*STAGE_BYTES;
        int kbase = kt*64;
        int c  = tid & 7;
        int rb = tid >> 3;           // 0..31
#pragma unroll
        for (int i = 0; i < 4; i++){
            int row = rb + i*32;
            uint32_t soff = (uint32_t)row*128u + (uint32_t)((c ^ (row & 7))<<4);
            cpa16(st + OFF_A + soff, A + s_aoff[row] + kbase + c*8);
        }
#pragma unroll
        for (int i = 0; i < 4; i++){
            int row = rb + i*32;
            uint32_t soff = (uint32_t)row*128u + (uint32_t)((c ^ (row & 7))<<4);
            cpa16(st + OFF_B + soff, B + s_boff[row] + kbase + c*8);
        }
    };

    // prologue: 2 stages in flight
    copy_stage(0, 0);
    asm volatile("cp.async.commit_group;" ::: "memory");
    copy_stage(1, 1);
    asm volatile("cp.async.commit_group;" ::: "memory");

    float acc[2][8][4];
#pragma unroll
    for (int a = 0; a < 2; a++)
#pragma unroll
        for (int b = 0; b < 8; b++)
#pragma unroll
            for (int c = 0; c < 4; c++) acc[a][b][c] = 0.0f;

    int arow0 = wm*32 + (lane & 15);
    int achk  = lane >> 4;                       // 0/1
    int bgrp  = lane >> 3;                       // 0..3
    int brow0 = wn*64 + (bgrp >> 1)*8 + (lane & 7);
    int bchk  = bgrp & 1;                        // 0/1

    for (int kt = 0; kt < NK; kt++){
        // at loop top, commits issued = min(kt+2, NK); need stage kt complete
        if (kt + 1 < NK) asm volatile("cp.async.wait_group 1;" ::: "memory");
        else             asm volatile("cp.async.wait_group 0;" ::: "memory");
        __syncthreads();   // all warps done reading stage kt-1 -> its buffer reusable

        if (kt + 2 < NK){
            copy_stage(kt + 2, (kt + 2) % 3);
            asm volatile("cp.async.commit_group;" ::: "memory");
        }

        uint32_t st = sm + (kt % 3)*STAGE_BYTES;
#pragma unroll
        for (int ks = 0; ks < 4; ks++){
            uint32_t fa[2][4], fb[4][4];
#pragma unroll
            for (int mt = 0; mt < 2; mt++){
                int r  = arow0 + mt*16;
                int ch = ks*2 + achk;
                uint32_t sa = (uint32_t)r*128u + (uint32_t)(((ch ^ (r & 7)) & 7)<<4);
                ldm_x4(fa[mt], st + OFF_A + sa);
            }
#pragma unroll
            for (int ntp = 0; ntp < 4; ntp++){
                int r  = brow0 + ntp*16;
                int ch = ks*2 + bchk;
                uint32_t sb = (uint32_t)r*128u + (uint32_t)(((ch ^ (r & 7)) & 7)<<4);
                ldm_x4(fb[ntp], st + OFF_B + sb);
            }
#pragma unroll
            for (int ntp = 0; ntp < 4; ntp++){
#pragma unroll
                for (int mt = 0; mt < 2; mt++){
                    mma16816(acc[mt][2*ntp  ], fa[mt], fb[ntp]    );
                    mma16816(acc[mt][2*ntp+1], fa[mt], fb[ntp] + 2);
                }
            }
        }
    }

    // epilogue
    int g   = lane >> 2;
    int tgi = lane & 3;
#pragma unroll
    for (int mt = 0; mt < 2; mt++){
#pragma unroll
        for (int h = 0; h < 2; h++){
            int r = wm*32 + mt*16 + g + h*8;
            int m = m0 + r;
            if (EXPERT && m >= cnt) continue;
            if (EXPERT){
                // scatter-add w*(acc+bias) into combined token buffer.
                // Exactly 2 contributions per element onto a zeroed buffer ->
                // order-independent fp32 result.
                float w = g_pair_w[base + m];
                size_t rowbase = (size_t)s_atok[r] * DOWND;
#pragma unroll
                for (int nt = 0; nt < 8; nt++){
                    int col = n0 + wn*64 + nt*8 + tgi*2;
                    float2 v;
                    v.x = (acc[mt][nt][2*h+0] + __ldg(bptr + col    )) * w;
                    v.y = (acc[mt][nt][2*h+1] + __ldg(bptr + col + 1)) * w;
                    atomicAdd((float2*)&C[rowbase + col], v);
                }
            } else {
                size_t rowbase = (size_t)m * HID;
#pragma unroll
                for (int nt = 0; nt < 8; nt++){
                    int col = n0 + wn*64 + nt*8 + tgi*2;
                    float2 v;
                    v.x = acc[mt][nt][2*h+0] + __ldg(bptr + col    );
                    v.y = acc[mt][nt][2*h+1] + __ldg(bptr + col + 1);
                    *(float2*)&C[rowbase + col] = v;
                }
            }
        }
    }
}

// ---------------- gelu over combined buffer -> fp16 ----------------
__global__ void k_combine(const float* __restrict__ comb, __half* __restrict__ hh){
    int i = blockIdx.x * blockDim.x + threadIdx.x;
    float4 v = ((const float4*)comb)[i];
    float g0 = gelu_new(v.x);
    float g1 = gelu_new(v.y);
    float g2 = gelu_new(v.z);
    float g3 = gelu_new(v.w);
    ((__half2*)hh)[2*i]   = __floats2half2_rn(g0, g1);
    ((__half2*)hh)[2*i+1] = __floats2half2_rn(g2, g3);
}

// ---------------- launch ----------------
extern "C" void kernel_launch(void* const* d_in, const int* in_sizes, int n_in,
                              void* d_out, int out_size){
    const float* x      = (const float*)d_in[0];
    const float* gate_w = (const float*)d_in[1];
    const float* down_w = (const float*)d_in[2];
    const float* down_b = (const float*)d_in[3];
    const float* up_w   = (const float*)d_in[4];
    const float* up_b   = (const float*)d_in[5];
    float* out = (float*)d_out;

    void *p_xh, *p_wh, *p_uh, *p_hh, *p_comb;
    cudaGetSymbolAddress(&p_xh,   g_xh);
    cudaGetSymbolAddress(&p_wh,   g_wh);
    cudaGetSymbolAddress(&p_uh,   g_uh);
    cudaGetSymbolAddress(&p_hh,   g_hh);
    cudaGetSymbolAddress(&p_comb, g_comb);

    cudaFuncSetAttribute(k_gemm<true,  HID>,   cudaFuncAttributeMaxDynamicSharedMemorySize, GSMEM);
    cudaFuncSetAttribute(k_gemm<false, DOWND>, cudaFuncAttributeMaxDynamicSharedMemorySize, GSMEM);

    // R12-identical preamble
    k_zero<<<(NTOK*DOWND/4)/256, 256>>>((float*)p_comb);
    k_gate<<<NTOK/32, 256>>>(x, gate_w, (__half*)p_xh);
    k_prefix<<<1, 1>>>(out + (size_t)NTOK * HID);   // loss scalar after [B,S,HIDDEN]
    k_scatter<<<NTOK/256, 256>>>();
    k_cvt1<<<(N4_DW + N4_UW + 255)/256, 256>>>(down_w, (__half*)p_wh, up_w, (__half*)p_uh);

    // grouped expert GEMM with fused scatter-add combine
    dim3 ge(64, DOWND/128, NE);
    k_gemm<true, HID><<<ge, 256, GSMEM>>>(
        (const __half*)p_xh, (const __half*)p_wh, down_b, (float*)p_comb);

    k_combine<<<(NTOK*DOWND/4)/256, 256>>>((const float*)p_comb, (__half*)p_hh);

    // up projection: out = h . up_w^T + up_b
    dim3 gu(NTOK/128, HID/128);
    k_gemm<false, DOWND><<<gu, 256, GSMEM>>>(
        (const __half*)p_hh, (const __half*)p_uh, up_b, out);
}